// round 11
// baseline (speedup 1.0000x reference)
#include <cuda_runtime.h>
#include <cuda_fp16.h>
#include <cstdint>

// VanillaRNN via warp-level HMMA, fp16 3-pass hi/lo split.
// R11 = R6 + (a) odd warps run k-loop rotated by 8 to decorrelate SMSP-mate
// stalls, (b) split bar.arrive/bar.sync per step so epilogue tails overlap
// the next step's independent work.

#define BATCH 2048
#define SEQT  512
#define HDIM  256
#define NCOL  16
#define NBLK  128
#define NTHR  256
#define NSTEPS 510
#define SCALE   256.0f
#define INVSCALE 0.00390625f

// smem byte offsets
#define SM_W   0          // init: W_hi staging; steady: W_lo*2^8 [256 rows][512B]
#define SM_B   131072     // h buffers: [buf0 hi 8K | lo 8K][buf1 hi 8K | lo 8K]
#define SM_XR  163840     // x ring: 2 slots x 16 f32
#define SM_TOTAL 163968

__device__ __forceinline__ uint32_t s2u(const void* p) {
    uint32_t a;
    asm("{ .reg .u64 t; cvta.to.shared.u64 t, %1; cvt.u32.u64 %0, t; }" : "=r"(a) : "l"(p));
    return a;
}

#define LDSM4(r, a)                                                               \
    asm volatile("ldmatrix.sync.aligned.m8n8.x4.shared.b16 {%0,%1,%2,%3}, [%4];"  \
                 : "=r"((r)[0]), "=r"((r)[1]), "=r"((r)[2]), "=r"((r)[3])         \
                 : "r"(a))

__device__ __forceinline__ void mma_f32(float* d, const uint32_t* a,
                                        uint32_t b0, uint32_t b1) {
    asm volatile("mma.sync.aligned.m16n8k16.row.col.f32.f16.f16.f32 "
                 "{%0,%1,%2,%3}, {%4,%5,%6,%7}, {%8,%9}, {%0,%1,%2,%3};"
                 : "+f"(d[0]), "+f"(d[1]), "+f"(d[2]), "+f"(d[3])
                 : "r"(a[0]), "r"(a[1]), "r"(a[2]), "r"(a[3]), "r"(b0), "r"(b1));
}
__device__ __forceinline__ void mma_f16(uint32_t* d, const uint32_t* a,
                                        uint32_t b0, uint32_t b1) {
    asm volatile("mma.sync.aligned.m16n8k16.row.col.f16.f16.f16.f16 "
                 "{%0,%1}, {%2,%3,%4,%5}, {%6,%7}, {%0,%1};"
                 : "+r"(d[0]), "+r"(d[1])
                 : "r"(a[0]), "r"(a[1]), "r"(a[2]), "r"(a[3]), "r"(b0), "r"(b1));
}

#define BAR_ARRIVE() asm volatile("bar.arrive 1, 512;" ::: "memory")
#define BAR_SYNC()   asm volatile("bar.sync 1, 512;" ::: "memory")

__device__ __forceinline__ float tanh_fast(float v) {
    float e = __expf(2.0f * v);
    return 1.0f - __fdividef(2.0f, e + 1.0f);
}

// one k-step of the 3-pass MMA (ks must be a compile-time constant)
#define KSTEP(ks) do {                                                            \
    const uint32_t _ch = (uint32_t)(((2 * (ks) + lx) ^ l7) << 4);                 \
    uint32_t _bh[4], _bl[4], _al0[4], _al1[4];                                    \
    LDSM4(_bh, rowB + _ch);                                                       \
    LDSM4(_bl, rowB + 8192 + _ch);                                                \
    LDSM4(_al0, rowAL0 + _ch);                                                    \
    LDSM4(_al1, rowAL1 + _ch);                                                    \
    mma_f32(&d32[0],  ahi0[ks], _bh[0], _bh[2]);                                  \
    mma_f32(&d32[4],  ahi0[ks], _bh[1], _bh[3]);                                  \
    mma_f32(&d32[8],  ahi1[ks], _bh[0], _bh[2]);                                  \
    mma_f32(&d32[12], ahi1[ks], _bh[1], _bh[3]);                                  \
    mma_f16(dlo[0], _al0,     _bh[0], _bh[2]);                                    \
    mma_f16(dlo[0], ahi0[ks], _bl[0], _bl[2]);                                    \
    mma_f16(dlo[1], _al0,     _bh[1], _bh[3]);                                    \
    mma_f16(dlo[1], ahi0[ks], _bl[1], _bl[3]);                                    \
    mma_f16(dlo[2], _al1,     _bh[0], _bh[2]);                                    \
    mma_f16(dlo[2], ahi1[ks], _bl[0], _bl[2]);                                    \
    mma_f16(dlo[3], _al1,     _bh[1], _bh[3]);                                    \
    mma_f16(dlo[3], ahi1[ks], _bl[1], _bl[3]);                                    \
} while (0)

__global__ void __launch_bounds__(NTHR, 1) VanillaRNN_54984171323420_kernel(
    const float* __restrict__ x,    // [2048, 512]
    const float* __restrict__ Whx,  // [256, 1]
    const float* __restrict__ Whh,  // [256, 256]
    const float* __restrict__ Wph,  // [10, 256]
    const float* __restrict__ bh,   // [256, 2048]
    const float* __restrict__ bp,   // [10, 2048]
    float* __restrict__ out)        // [2048, 10]
{
    extern __shared__ char smc[];
    const uint32_t sb = s2u(smc);
    const int tid = threadIdx.x;
    const int w = tid >> 5;          // warp 0..7 -> m rows [32w, 32w+32)
    const int l = tid & 31;
    const int lq = l >> 2;
    const int lr = (l & 3) * 2;
    const int lx = l >> 4;
    const int l7 = l & 7;
    const int m0 = 32 * w;
    const int j0 = blockIdx.x * NCOL;
    const bool wodd = (w & 1);

    // ---------------- stage W_hi into smem (swizzled 512B rows) ----------------
    for (int idx = tid; idx < HDIM * HDIM; idx += NTHR) {
        int m = idx >> 8, k = idx & 255;
        __half hi = __float2half_rn(Whh[idx]);
        uint32_t ch = (uint32_t)(((k >> 3) ^ (m & 7)) << 4);
        *(__half*)(smc + SM_W + m * 512 + ch + (k & 7) * 2) = hi;
    }
    float xn1 = 0.0f;
    if (tid < NCOL) {
        const float* xr = x + (j0 + tid) * SEQT;
        *(float*)(smc + SM_XR + 64 + tid * 4) = xr[0];
        xn1 = xr[1];
    }
    __syncthreads();

    // ---------------- A_hi fragments -> registers (loop-invariant, 128 regs) ----
    const uint32_t rowAL0 = sb + SM_W + (uint32_t)(m0 + (l & 15)) * 512;
    const uint32_t rowAL1 = rowAL0 + 16 * 512;
    uint32_t ahi0[16][4], ahi1[16][4];
#pragma unroll
    for (int ks = 0; ks < 16; ks++) {
        const uint32_t ch = (uint32_t)(((2 * ks + lx) ^ l7) << 4);
        LDSM4(ahi0[ks], rowAL0 + ch);
        LDSM4(ahi1[ks], rowAL1 + ch);
    }
    __syncthreads();

    // ---------------- overwrite staging with W_lo * 2^8 ----------------
    for (int idx = tid; idx < HDIM * HDIM; idx += NTHR) {
        int m = idx >> 8, k = idx & 255;
        float wv = Whh[idx];
        __half hi = __float2half_rn(wv);
        __half lo = __float2half_rn((wv - __half2float(hi)) * SCALE);
        uint32_t ch = (uint32_t)(((k >> 3) ^ (m & 7)) << 4);
        *(__half*)(smc + SM_W + m * 512 + ch + (k & 7) * 2) = lo;
    }

    // ---------------- bias / Whx fragments (regs) ----------------
    float bias[16];
    float wx[2][2];
#pragma unroll
    for (int tm = 0; tm < 2; tm++) {
        wx[tm][0] = Whx[m0 + 16 * tm + lq];
        wx[tm][1] = Whx[m0 + 16 * tm + lq + 8];
#pragma unroll
        for (int tn = 0; tn < 2; tn++)
#pragma unroll
            for (int e = 0; e < 4; e++) {
                int m = m0 + 16 * tm + lq + ((e >> 1) ? 8 : 0);
                int n = 8 * tn + lr + (e & 1);
                bias[tm * 8 + tn * 4 + e] = bh[m * BATCH + j0 + n];
            }
    }

    // ---------------- prologue: h1 = tanh(b_h + Whx*x_0) -> buf0 ----------------
#pragma unroll
    for (int tm = 0; tm < 2; tm++)
#pragma unroll
        for (int tn = 0; tn < 2; tn++)
#pragma unroll
            for (int e = 0; e < 4; e++) {
                int n = 8 * tn + lr + (e & 1);
                int mh = e >> 1;
                int m = m0 + 16 * tm + lq + (mh ? 8 : 0);
                float xv = *(const float*)(smc + SM_XR + 64 + n * 4);
                float h = tanh_fast(bias[tm * 8 + tn * 4 + e] + wx[tm][mh] * xv);
                __half hi = __float2half_rn(h);
                __half lo = __float2half_rn((h - __half2float(hi)) * SCALE);
                uint32_t off = (uint32_t)n * 512 + ((((uint32_t)m >> 3) ^ (n & 7)) << 4) + (m & 7) * 2;
                *(__half*)(smc + SM_B + off) = hi;
                *(__half*)(smc + SM_B + 8192 + off) = lo;
            }
    if (tid < NCOL) *(float*)(smc + SM_XR + tid * 4) = xn1;  // slot0 <- x_1
    __syncthreads();
    BAR_ARRIVE();                     // balance the first in-loop BAR_SYNC

    const uint32_t rowBb = sb + SM_B + (uint32_t)(l & 15) * 512;

    // ================= recurrence: 510 HMMA steps, split bar/step =================
#pragma unroll 1
    for (int it = 0; it < NSTEPS; it++) {
        const int p = it & 1;                 // read buf p, write buf 1-p
        // ---- pre-sync zone: work independent of the new h buffer ----
        float xnext = 0.0f;
        if (tid < NCOL) xnext = x[(j0 + tid) * SEQT + it + 2];

        float d32[16];
#pragma unroll
        for (int q = 0; q < 16; q++) d32[q] = bias[q];
        uint32_t dlo[4][2];
#pragma unroll
        for (int q = 0; q < 4; q++) { dlo[q][0] = 0u; dlo[q][1] = 0u; }

        const uint32_t rowB = rowBb + (uint32_t)p * 16384;

        BAR_SYNC();                           // h(it+1) stores from all warps visible

        // ---- k-loop: odd warps rotated by 8 to decorrelate SMSP-mate stalls ----
        if (wodd) {
            KSTEP(8);  KSTEP(9);  KSTEP(10); KSTEP(11);
            KSTEP(12); KSTEP(13); KSTEP(14); KSTEP(15);
            KSTEP(0);  KSTEP(1);  KSTEP(2);  KSTEP(3);
            KSTEP(4);  KSTEP(5);  KSTEP(6);  KSTEP(7);
        } else {
            KSTEP(0);  KSTEP(1);  KSTEP(2);  KSTEP(3);
            KSTEP(4);  KSTEP(5);  KSTEP(6);  KSTEP(7);
            KSTEP(8);  KSTEP(9);  KSTEP(10); KSTEP(11);
            KSTEP(12); KSTEP(13); KSTEP(14); KSTEP(15);
        }

        // ---- epilogue: h = tanh(d32 + dlo*2^-8 + Whx*x) -> buf 1-p ----
        const uint32_t xsl = (uint32_t)(SM_XR + p * 64);
        const uint32_t bufw = (uint32_t)(SM_B + (1 - p) * 16384);
#pragma unroll
        for (int tm = 0; tm < 2; tm++)
#pragma unroll
            for (int tn = 0; tn < 2; tn++) {
                float2 lo01 = __half22float2(*(__half2*)&dlo[tm * 2 + tn][0]);
                float2 lo23 = __half22float2(*(__half2*)&dlo[tm * 2 + tn][1]);
                float lov[4] = {lo01.x, lo01.y, lo23.x, lo23.y};
#pragma unroll
                for (int e = 0; e < 4; e++) {
                    int idx = tm * 8 + tn * 4 + e;
                    int n = 8 * tn + lr + (e & 1);
                    int mh = e >> 1;
                    int m = m0 + 16 * tm + lq + (mh ? 8 : 0);
                    float xv = *(const float*)(smc + xsl + n * 4);
                    float pre = fmaf(wx[tm][mh], xv, fmaf(lov[e], INVSCALE, d32[idx]));
                    float h = tanh_fast(pre);
                    __half hi = __float2half_rn(h);
                    __half lo = __float2half_rn((h - __half2float(hi)) * SCALE);
                    uint32_t off = (uint32_t)n * 512 + ((((uint32_t)m >> 3) ^ (n & 7)) << 4) + (m & 7) * 2;
                    *(__half*)(smc + bufw + off) = hi;
                    *(__half*)(smc + bufw + 8192 + off) = lo;
                }
            }
        if (tid < NCOL) *(float*)(smc + SM_XR + (1 - p) * 64 + tid * 4) = xnext;
        BAR_ARRIVE();                         // my h(it+2)/x stores are done
    }
    __syncthreads();

    // ================= projection: out = Wph @ h + bp =================
    // final h lives in buf0 (it=509 wrote buf 1-p = 0)
    if (tid < 10 * NCOL) {
        const int c = tid >> 4, j = tid & 15;
        float s = bp[c * BATCH + j0 + j];
        const float* wr = Wph + c * HDIM;
#pragma unroll 8
        for (int k = 0; k < HDIM; k++) {
            uint32_t off = (uint32_t)j * 512 + ((((uint32_t)k >> 3) ^ (j & 7)) << 4) + (k & 7) * 2;
            float hv = __half2float(*(__half*)(smc + SM_B + off)) +
                       __half2float(*(__half*)(smc + SM_B + 8192 + off)) * INVSCALE;
            s = fmaf(wr[k], hv, s);
        }
        out[(j0 + j) * 10 + c] = s;
    }
}

extern "C" void kernel_launch(void* const* d_in, const int* in_sizes, int n_in,
                              void* d_out, int out_size) {
    const float* x   = (const float*)d_in[0];
    const float* Whx = (const float*)d_in[1];
    const float* Whh = (const float*)d_in[2];
    const float* Wph = (const float*)d_in[3];
    const float* bh  = (const float*)d_in[4];
    const float* bp  = (const float*)d_in[5];
    float* out = (float*)d_out;

    cudaFuncSetAttribute(VanillaRNN_54984171323420_kernel,
                         cudaFuncAttributeMaxDynamicSharedMemorySize, SM_TOTAL);
    VanillaRNN_54984171323420_kernel<<<NBLK, NTHR, SM_TOTAL>>>(
        x, Whx, Whh, Wph, bh, bp, out);
}

// round 12
// speedup vs baseline: 1.4122x; 1.4122x over previous
#include <cuda_runtime.h>
#include <cuda_fp16.h>
#include <cstdint>

// VanillaRNN via warp-level HMMA, fp16 3-pass hi/lo split.
// R12 = R6 with h stored K-MAJOR (row = hidden idx, 32B rows, 16B-chunk
// swizzle): B loaded via ldmatrix.trans (lane-invariant base + ks*512),
// epilogue h stores become paired STS.32, pair conversions via f16x2.

#define BATCH 2048
#define SEQT  512
#define HDIM  256
#define NCOL  16
#define NBLK  128
#define NTHR  256
#define NSTEPS 510
#define SCALE   256.0f
#define INVSCALE 0.00390625f

// smem byte offsets
#define SM_W   0          // init: W_hi staging; steady: W_lo*2^8 [256 rows][512B]
#define SM_B   131072     // h buffers: [buf0 hi 8K | lo 8K][buf1 hi 8K | lo 8K]
#define SM_XR  163840     // x ring: 2 slots x 16 f32
#define SM_TOTAL 163968

__device__ __forceinline__ uint32_t s2u(const void* p) {
    uint32_t a;
    asm("{ .reg .u64 t; cvta.to.shared.u64 t, %1; cvt.u32.u64 %0, t; }" : "=r"(a) : "l"(p));
    return a;
}

#define LDSM4(r, a)                                                               \
    asm volatile("ldmatrix.sync.aligned.m8n8.x4.shared.b16 {%0,%1,%2,%3}, [%4];"  \
                 : "=r"((r)[0]), "=r"((r)[1]), "=r"((r)[2]), "=r"((r)[3])         \
                 : "r"(a))
#define LDSM4T(r, a)                                                              \
    asm volatile("ldmatrix.sync.aligned.m8n8.x4.trans.shared.b16 {%0,%1,%2,%3}, [%4];" \
                 : "=r"((r)[0]), "=r"((r)[1]), "=r"((r)[2]), "=r"((r)[3])         \
                 : "r"(a))

__device__ __forceinline__ void mma_f32(float* d, const uint32_t* a,
                                        uint32_t b0, uint32_t b1) {
    asm volatile("mma.sync.aligned.m16n8k16.row.col.f32.f16.f16.f32 "
                 "{%0,%1,%2,%3}, {%4,%5,%6,%7}, {%8,%9}, {%0,%1,%2,%3};"
                 : "+f"(d[0]), "+f"(d[1]), "+f"(d[2]), "+f"(d[3])
                 : "r"(a[0]), "r"(a[1]), "r"(a[2]), "r"(a[3]), "r"(b0), "r"(b1));
}
__device__ __forceinline__ void mma_f16(uint32_t* d, const uint32_t* a,
                                        uint32_t b0, uint32_t b1) {
    asm volatile("mma.sync.aligned.m16n8k16.row.col.f16.f16.f16.f16 "
                 "{%0,%1}, {%2,%3,%4,%5}, {%6,%7}, {%0,%1};"
                 : "+r"(d[0]), "+r"(d[1])
                 : "r"(a[0]), "r"(a[1]), "r"(a[2]), "r"(a[3]), "r"(b0), "r"(b1));
}

__device__ __forceinline__ float tanh_fast(float v) {
    float e = __expf(2.0f * v);
    return 1.0f - __fdividef(2.0f, e + 1.0f);
}

// k-major h address: element (hidden k, batch n) at
//   k*32 + ((n>>3) ^ ((k>>2)&1))*16 + (n&7)*2
__device__ __forceinline__ uint32_t haddr(int k, int n) {
    return (uint32_t)k * 32 + ((((uint32_t)n >> 3) ^ (((uint32_t)k >> 2) & 1)) << 4) +
           ((uint32_t)n & 7) * 2;
}

__global__ void __launch_bounds__(NTHR, 1) VanillaRNN_54984171323420_kernel(
    const float* __restrict__ x,    // [2048, 512]
    const float* __restrict__ Whx,  // [256, 1]
    const float* __restrict__ Whh,  // [256, 256]
    const float* __restrict__ Wph,  // [10, 256]
    const float* __restrict__ bh,   // [256, 2048]
    const float* __restrict__ bp,   // [10, 2048]
    float* __restrict__ out)        // [2048, 10]
{
    extern __shared__ char smc[];
    const uint32_t sb = s2u(smc);
    const int tid = threadIdx.x;
    const int w = tid >> 5;          // warp 0..7 -> m rows [32w, 32w+32)
    const int l = tid & 31;
    const int lq = l >> 2;
    const int lr = (l & 3) * 2;
    const int lx = l >> 4;
    const int l7 = l & 7;
    const int m0 = 32 * w;
    const int j0 = blockIdx.x * NCOL;

    // ---------------- stage W_hi into smem (swizzled 512B rows) ----------------
    for (int idx = tid; idx < HDIM * HDIM; idx += NTHR) {
        int m = idx >> 8, k = idx & 255;
        __half hi = __float2half_rn(Whh[idx]);
        uint32_t ch = (uint32_t)(((k >> 3) ^ (m & 7)) << 4);
        *(__half*)(smc + SM_W + m * 512 + ch + (k & 7) * 2) = hi;
    }
    float xn1 = 0.0f;
    if (tid < NCOL) {
        const float* xr = x + (j0 + tid) * SEQT;
        *(float*)(smc + SM_XR + 64 + tid * 4) = xr[0];   // slot1 = x_0
        xn1 = xr[1];
    }
    __syncthreads();

    // ---------------- A_hi fragments -> registers (loop-invariant, 128 regs) ----
    const uint32_t rowAL0 = sb + SM_W + (uint32_t)(m0 + (l & 15)) * 512;
    const uint32_t rowAL1 = rowAL0 + 16 * 512;
    uint32_t ahi0[16][4], ahi1[16][4];
#pragma unroll
    for (int ks = 0; ks < 16; ks++) {
        const uint32_t ch = (uint32_t)(((2 * ks + lx) ^ l7) << 4);
        LDSM4(ahi0[ks], rowAL0 + ch);
        LDSM4(ahi1[ks], rowAL1 + ch);
    }
    __syncthreads();

    // ---------------- overwrite staging with W_lo * 2^8 ----------------
    for (int idx = tid; idx < HDIM * HDIM; idx += NTHR) {
        int m = idx >> 8, k = idx & 255;
        float wv = Whh[idx];
        __half hi = __float2half_rn(wv);
        __half lo = __float2half_rn((wv - __half2float(hi)) * SCALE);
        uint32_t ch = (uint32_t)(((k >> 3) ^ (m & 7)) << 4);
        *(__half*)(smc + SM_W + m * 512 + ch + (k & 7) * 2) = lo;
    }

    // ---------------- bias / Whx fragments; packed store bases ----------------
    float bias[16];
    float wx[2][2];
    uint32_t sb8[4];                 // store bases: [tm*2+d] = {tn0 | tn1<<16}
#pragma unroll
    for (int tm = 0; tm < 2; tm++) {
        wx[tm][0] = Whx[m0 + 16 * tm + lq];
        wx[tm][1] = Whx[m0 + 16 * tm + lq + 8];
#pragma unroll
        for (int d = 0; d < 2; d++) {
            int m = m0 + 16 * tm + 8 * d + lq;
            uint32_t b0 = haddr(m, lr);          // tn = 0
            uint32_t b1 = haddr(m, 8 + lr);      // tn = 1
            sb8[tm * 2 + d] = b0 | (b1 << 16);
        }
#pragma unroll
        for (int tn = 0; tn < 2; tn++)
#pragma unroll
            for (int e = 0; e < 4; e++) {
                int m = m0 + 16 * tm + lq + ((e >> 1) ? 8 : 0);
                int n = 8 * tn + lr + (e & 1);
                bias[tm * 8 + tn * 4 + e] = bh[m * BATCH + j0 + n];
            }
    }

    // ---------------- prologue: h1 = tanh(b_h + Whx*x_0) -> buf0 ----------------
#pragma unroll
    for (int tm = 0; tm < 2; tm++)
#pragma unroll
        for (int tn = 0; tn < 2; tn++) {
            float hv[4];
#pragma unroll
            for (int e = 0; e < 4; e++) {
                int n = 8 * tn + lr + (e & 1);
                float xv = *(const float*)(smc + SM_XR + 64 + n * 4);
                hv[e] = tanh_fast(bias[tm * 8 + tn * 4 + e] + wx[tm][e >> 1] * xv);
            }
#pragma unroll
            for (int d = 0; d < 2; d++) {
                float h0 = hv[2 * d], h1 = hv[2 * d + 1];
                __half2 hi2 = __floats2half2_rn(h0, h1);
                __half2 lo2 = __floats2half2_rn((h0 - __low2float(hi2)) * SCALE,
                                                (h1 - __high2float(hi2)) * SCALE);
                uint32_t ba = (sb8[tm * 2 + d] >> (16 * tn)) & 0xFFFFu;
                *(uint32_t*)(smc + SM_B + ba) = *(uint32_t*)&hi2;
                *(uint32_t*)(smc + SM_B + 8192 + ba) = *(uint32_t*)&lo2;
            }
        }
    if (tid < NCOL) *(float*)(smc + SM_XR + tid * 4) = xn1;  // slot0 <- x_1
    __syncthreads();

    // ---- lane-invariant B base (trans ldmatrix: lane supplies k-row address) ----
    // mat = l>>3: 0:(k0-7,n0-7) 1:(k8-15,n0-7) 2:(k0-7,n8-15) 3:(k8-15,n8-15)
    const uint32_t krb = (uint32_t)(((l >> 3) & 1) * 8 + l7);
    const uint32_t nck = (uint32_t)(l >> 4);
    const uint32_t rowBb = sb + SM_B + krb * 32 + ((nck ^ ((krb >> 2) & 1)) << 4);

    // ================= recurrence: 510 HMMA steps, 1 bar/step =================
#pragma unroll 2
    for (int it = 0; it < NSTEPS; it++) {
        const int p = it & 1;                 // read buf p, write buf 1-p
        float xnext = 0.0f;
        if (tid < NCOL) xnext = x[(j0 + tid) * SEQT + it + 2];

        const uint32_t rowBt = rowBb + (uint32_t)p * 16384;

        float d32[16];
#pragma unroll
        for (int q = 0; q < 16; q++) d32[q] = bias[q];
        uint32_t dlo[4][2];
#pragma unroll
        for (int q = 0; q < 4; q++) { dlo[q][0] = 0u; dlo[q][1] = 0u; }

#pragma unroll
        for (int ks = 0; ks < 16; ks++) {
            const uint32_t ch = (uint32_t)(((2 * ks + lx) ^ l7) << 4);
            uint32_t bh4[4], bl4[4], al0[4], al1[4];
            LDSM4T(bh4, rowBt + (uint32_t)ks * 512);
            LDSM4T(bl4, rowBt + 8192 + (uint32_t)ks * 512);
            LDSM4(al0, rowAL0 + ch);
            LDSM4(al1, rowAL1 + ch);
            // main pass: W_hi . h_hi  (f32 accum); n-tile0 = bh4[0],[1]
            mma_f32(&d32[0],  ahi0[ks], bh4[0], bh4[1]);
            mma_f32(&d32[4],  ahi0[ks], bh4[2], bh4[3]);
            mma_f32(&d32[8],  ahi1[ks], bh4[0], bh4[1]);
            mma_f32(&d32[12], ahi1[ks], bh4[2], bh4[3]);
            // correction passes (x 2^8): f16 accum
            mma_f16(dlo[0], al0,      bh4[0], bh4[1]);
            mma_f16(dlo[0], ahi0[ks], bl4[0], bl4[1]);
            mma_f16(dlo[1], al0,      bh4[2], bh4[3]);
            mma_f16(dlo[1], ahi0[ks], bl4[2], bl4[3]);
            mma_f16(dlo[2], al1,      bh4[0], bh4[1]);
            mma_f16(dlo[2], ahi1[ks], bl4[0], bl4[1]);
            mma_f16(dlo[3], al1,      bh4[2], bh4[3]);
            mma_f16(dlo[3], ahi1[ks], bl4[2], bl4[3]);
        }

        // ---- epilogue: h = tanh(d32 + dlo*2^-8 + Whx*x) -> buf 1-p ----
        const uint32_t xsl = (uint32_t)(SM_XR + p * 64);
        const uint32_t bufw = (uint32_t)(SM_B + (1 - p) * 16384);
        const float2 xva = *(const float2*)(smc + xsl + lr * 4);        // n = lr, lr+1
        const float2 xvb = *(const float2*)(smc + xsl + 32 + lr * 4);   // n = 8+lr, +1
#pragma unroll
        for (int tm = 0; tm < 2; tm++)
#pragma unroll
            for (int tn = 0; tn < 2; tn++) {
                float2 lo01 = __half22float2(*(__half2*)&dlo[tm * 2 + tn][0]);
                float2 lo23 = __half22float2(*(__half2*)&dlo[tm * 2 + tn][1]);
                float lov[4] = {lo01.x, lo01.y, lo23.x, lo23.y};
                const float xve = tn ? xvb.x : xva.x;
                const float xvo = tn ? xvb.y : xva.y;
                float hv[4];
#pragma unroll
                for (int e = 0; e < 4; e++) {
                    int q = tm * 8 + tn * 4 + e;
                    float xv = (e & 1) ? xvo : xve;
                    float pre = fmaf(wx[tm][e >> 1], xv, fmaf(lov[e], INVSCALE, d32[q]));
                    hv[e] = tanh_fast(pre);
                }
#pragma unroll
                for (int d = 0; d < 2; d++) {
                    float h0 = hv[2 * d], h1 = hv[2 * d + 1];
                    __half2 hi2 = __floats2half2_rn(h0, h1);
                    __half2 lo2 = __floats2half2_rn((h0 - __low2float(hi2)) * SCALE,
                                                    (h1 - __high2float(hi2)) * SCALE);
                    uint32_t ba = (sb8[tm * 2 + d] >> (16 * tn)) & 0xFFFFu;
                    *(uint32_t*)(smc + bufw + ba) = *(uint32_t*)&hi2;
                    *(uint32_t*)(smc + bufw + 8192 + ba) = *(uint32_t*)&lo2;
                }
            }
        if (tid < NCOL) *(float*)(smc + SM_XR + (1 - p) * 64 + tid * 4) = xnext;
        __syncthreads();
    }

    // ================= projection: out = Wph @ h + bp =================
    // final h lives in buf0 (it=509 wrote buf 1-p = 0)
    if (tid < 10 * NCOL) {
        const int c = tid >> 4, j = tid & 15;
        float s = bp[c * BATCH + j0 + j];
        const float* wr = Wph + c * HDIM;
#pragma unroll 8
        for (int k = 0; k < HDIM; k++) {
            uint32_t off = haddr(k, j);
            float hv = __half2float(*(__half*)(smc + SM_B + off)) +
                       __half2float(*(__half*)(smc + SM_B + 8192 + off)) * INVSCALE;
            s = fmaf(wr[k], hv, s);
        }
        out[(j0 + j) * 10 + c] = s;
    }
}

extern "C" void kernel_launch(void* const* d_in, const int* in_sizes, int n_in,
                              void* d_out, int out_size) {
    const float* x   = (const float*)d_in[0];
    const float* Whx = (const float*)d_in[1];
    const float* Whh = (const float*)d_in[2];
    const float* Wph = (const float*)d_in[3];
    const float* bh  = (const float*)d_in[4];
    const float* bp  = (const float*)d_in[5];
    float* out = (float*)d_out;

    cudaFuncSetAttribute(VanillaRNN_54984171323420_kernel,
                         cudaFuncAttributeMaxDynamicSharedMemorySize, SM_TOTAL);
    VanillaRNN_54984171323420_kernel<<<NBLK, NTHR, SM_TOTAL>>>(
        x, Whx, Whh, Wph, bh, bp, out);
}

// round 13
// speedup vs baseline: 1.4320x; 1.0140x over previous
#include <cuda_runtime.h>
#include <cuda_fp16.h>
#include <cstdint>

// VanillaRNN via warp-level HMMA, fp16 3-pass hi/lo split.
// R13 = R12 + A_lo stored as e5m2 fp8 (scale 2^8) in per-fragment layout:
// one LDS.128 + 8 cvt per kstep replaces two LDSM.x4 — halves A_lo smem
// traffic, moves the work to the idle ALU pipe.

#define BATCH 2048
#define SEQT  512
#define HDIM  256
#define NCOL  16
#define NBLK  128
#define NTHR  256
#define NSTEPS 510
#define SCALE   256.0f
#define INVSCALE 0.00390625f

// smem byte offsets
#define SM_A8  0          // steady: A_lo e5m2 [8 warps][16 ks][32 lanes][16B] = 64KB
#define SM_W   0          // init only: W_hi staging [256 rows][512B] = 128KB (overlaps SM_A8)
#define SM_B   131072     // h buffers: [buf0 hi 8K | lo 8K][buf1 hi 8K | lo 8K]
#define SM_XR  163840     // x ring: 2 slots x 16 f32
#define SM_TOTAL 163968

__device__ __forceinline__ uint32_t s2u(const void* p) {
    uint32_t a;
    asm("{ .reg .u64 t; cvta.to.shared.u64 t, %1; cvt.u32.u64 %0, t; }" : "=r"(a) : "l"(p));
    return a;
}

#define LDSM4(r, a)                                                               \
    asm volatile("ldmatrix.sync.aligned.m8n8.x4.shared.b16 {%0,%1,%2,%3}, [%4];"  \
                 : "=r"((r)[0]), "=r"((r)[1]), "=r"((r)[2]), "=r"((r)[3])         \
                 : "r"(a))
#define LDSM4T(r, a)                                                              \
    asm volatile("ldmatrix.sync.aligned.m8n8.x4.trans.shared.b16 {%0,%1,%2,%3}, [%4];" \
                 : "=r"((r)[0]), "=r"((r)[1]), "=r"((r)[2]), "=r"((r)[3])         \
                 : "r"(a))

__device__ __forceinline__ void mma_f32(float* d, const uint32_t* a,
                                        uint32_t b0, uint32_t b1) {
    asm volatile("mma.sync.aligned.m16n8k16.row.col.f32.f16.f16.f32 "
                 "{%0,%1,%2,%3}, {%4,%5,%6,%7}, {%8,%9}, {%0,%1,%2,%3};"
                 : "+f"(d[0]), "+f"(d[1]), "+f"(d[2]), "+f"(d[3])
                 : "r"(a[0]), "r"(a[1]), "r"(a[2]), "r"(a[3]), "r"(b0), "r"(b1));
}
__device__ __forceinline__ void mma_f16(uint32_t* d, const uint32_t* a,
                                        uint32_t b0, uint32_t b1) {
    asm volatile("mma.sync.aligned.m16n8k16.row.col.f16.f16.f16.f16 "
                 "{%0,%1}, {%2,%3,%4,%5}, {%6,%7}, {%0,%1};"
                 : "+r"(d[0]), "+r"(d[1])
                 : "r"(a[0]), "r"(a[1]), "r"(a[2]), "r"(a[3]), "r"(b0), "r"(b1));
}

__device__ __forceinline__ float tanh_fast(float v) {
    float e = __expf(2.0f * v);
    return 1.0f - __fdividef(2.0f, e + 1.0f);
}

// unpack u32 of 4 e5m2 bytes -> two f16x2 regs (exact conversion)
__device__ __forceinline__ void unp2(uint32_t s, uint32_t& d0, uint32_t& d1) {
    uint16_t lo, hi;
    asm("mov.b32 {%0,%1}, %2;" : "=h"(lo), "=h"(hi) : "r"(s));
    asm("cvt.rn.f16x2.e5m2x2 %0, %1;" : "=r"(d0) : "h"(lo));
    asm("cvt.rn.f16x2.e5m2x2 %0, %1;" : "=r"(d1) : "h"(hi));
}
// encode one float -> e5m2 byte (low byte of the x2 result)
__device__ __forceinline__ uint8_t enc_e5m2(float v) {
    uint16_t r;
    asm("cvt.rn.satfinite.e5m2x2.f32 %0, %1, %2;" : "=h"(r) : "f"(0.0f), "f"(v));
    return (uint8_t)(r & 0xFF);
}

// k-major h address: element (hidden k, batch n)
__device__ __forceinline__ uint32_t haddr(int k, int n) {
    return (uint32_t)k * 32 + ((((uint32_t)n >> 3) ^ (((uint32_t)k >> 2) & 1)) << 4) +
           ((uint32_t)n & 7) * 2;
}

__global__ void __launch_bounds__(NTHR, 1) VanillaRNN_54984171323420_kernel(
    const float* __restrict__ x,    // [2048, 512]
    const float* __restrict__ Whx,  // [256, 1]
    const float* __restrict__ Whh,  // [256, 256]
    const float* __restrict__ Wph,  // [10, 256]
    const float* __restrict__ bh,   // [256, 2048]
    const float* __restrict__ bp,   // [10, 2048]
    float* __restrict__ out)        // [2048, 10]
{
    extern __shared__ char smc[];
    const uint32_t sb = s2u(smc);
    const int tid = threadIdx.x;
    const int w = tid >> 5;          // warp 0..7 -> m rows [32w, 32w+32)
    const int l = tid & 31;
    const int lq = l >> 2;
    const int lr = (l & 3) * 2;
    const int lx = l >> 4;
    const int l7 = l & 7;
    const int m0 = 32 * w;
    const int j0 = blockIdx.x * NCOL;

    // ---------------- stage W_hi into smem (swizzled 512B rows) ----------------
    for (int idx = tid; idx < HDIM * HDIM; idx += NTHR) {
        int m = idx >> 8, k = idx & 255;
        __half hi = __float2half_rn(Whh[idx]);
        uint32_t ch = (uint32_t)(((k >> 3) ^ (m & 7)) << 4);
        *(__half*)(smc + SM_W + m * 512 + ch + (k & 7) * 2) = hi;
    }
    float xn1 = 0.0f;
    if (tid < NCOL) {
        const float* xr = x + (j0 + tid) * SEQT;
        *(float*)(smc + SM_XR + 64 + tid * 4) = xr[0];   // slot1 = x_0
        xn1 = xr[1];
    }
    __syncthreads();

    // ---------------- A_hi fragments -> registers (loop-invariant, 128 regs) ----
    const uint32_t rowAL0 = sb + SM_W + (uint32_t)(m0 + (l & 15)) * 512;
    const uint32_t rowAL1 = rowAL0 + 16 * 512;
    uint32_t ahi0[16][4], ahi1[16][4];
#pragma unroll
    for (int ks = 0; ks < 16; ks++) {
        const uint32_t ch = (uint32_t)(((2 * ks + lx) ^ l7) << 4);
        LDSM4(ahi0[ks], rowAL0 + ch);
        LDSM4(ahi1[ks], rowAL1 + ch);
    }
    __syncthreads();

    // ------- overwrite staging with A_lo e5m2 (scale 2^8), fragment layout -------
    // element (m,k): warp=m>>5, lane=(m&7)*4+((k>>1)&3), ks=k>>4,
    // byte slot = ((m>>4)&1)*8 + (((k>>3)&1)*2+((m>>3)&1))*2 + (k&1)
    for (int idx = tid; idx < HDIM * HDIM; idx += NTHR) {
        int m = idx >> 8, k = idx & 255;
        float wv = Whh[idx];
        float lo = (wv - __half2float(__float2half_rn(wv))) * SCALE;
        int wdst = m >> 5;
        int lane = (m & 7) * 4 + ((k >> 1) & 3);
        int ks = k >> 4;
        int slot = ((m >> 4) & 1) * 8 + ((((k >> 3) & 1) * 2 + ((m >> 3) & 1)) << 1) + (k & 1);
        *(uint8_t*)(smc + SM_A8 + wdst * 8192 + ks * 512 + lane * 16 + slot) = enc_e5m2(lo);
    }

    // ---------------- bias / Whx fragments; packed store bases ----------------
    float bias[16];
    float wx[2][2];
    uint32_t sb8[4];                 // store bases: [tm*2+d] = {tn0 | tn1<<16}
#pragma unroll
    for (int tm = 0; tm < 2; tm++) {
        wx[tm][0] = Whx[m0 + 16 * tm + lq];
        wx[tm][1] = Whx[m0 + 16 * tm + lq + 8];
#pragma unroll
        for (int d = 0; d < 2; d++) {
            int m = m0 + 16 * tm + 8 * d + lq;
            uint32_t b0 = haddr(m, lr);          // tn = 0
            uint32_t b1 = haddr(m, 8 + lr);      // tn = 1
            sb8[tm * 2 + d] = b0 | (b1 << 16);
        }
#pragma unroll
        for (int tn = 0; tn < 2; tn++)
#pragma unroll
            for (int e = 0; e < 4; e++) {
                int m = m0 + 16 * tm + lq + ((e >> 1) ? 8 : 0);
                int n = 8 * tn + lr + (e & 1);
                bias[tm * 8 + tn * 4 + e] = bh[m * BATCH + j0 + n];
            }
    }

    // ---------------- prologue: h1 = tanh(b_h + Whx*x_0) -> buf0 ----------------
#pragma unroll
    for (int tm = 0; tm < 2; tm++)
#pragma unroll
        for (int tn = 0; tn < 2; tn++) {
            float hv[4];
#pragma unroll
            for (int e = 0; e < 4; e++) {
                int n = 8 * tn + lr + (e & 1);
                float xv = *(const float*)(smc + SM_XR + 64 + n * 4);
                hv[e] = tanh_fast(bias[tm * 8 + tn * 4 + e] + wx[tm][e >> 1] * xv);
            }
#pragma unroll
            for (int d = 0; d < 2; d++) {
                float h0 = hv[2 * d], h1 = hv[2 * d + 1];
                __half2 hi2 = __floats2half2_rn(h0, h1);
                __half2 lo2 = __floats2half2_rn((h0 - __low2float(hi2)) * SCALE,
                                                (h1 - __high2float(hi2)) * SCALE);
                uint32_t ba = (sb8[tm * 2 + d] >> (16 * tn)) & 0xFFFFu;
                *(uint32_t*)(smc + SM_B + ba) = *(uint32_t*)&hi2;
                *(uint32_t*)(smc + SM_B + 8192 + ba) = *(uint32_t*)&lo2;
            }
        }
    if (tid < NCOL) *(float*)(smc + SM_XR + tid * 4) = xn1;  // slot0 <- x_1
    __syncthreads();

    // ---- lane-invariant bases ----
    const uint32_t krb = (uint32_t)(((l >> 3) & 1) * 8 + l7);
    const uint32_t nck = (uint32_t)(l >> 4);
    const uint32_t rowBb = sb + SM_B + krb * 32 + ((nck ^ ((krb >> 2) & 1)) << 4);
    const char* fp8b = smc + SM_A8 + w * 8192 + l * 16;

    // ================= recurrence: 510 HMMA steps, 1 bar/step =================
#pragma unroll 2
    for (int it = 0; it < NSTEPS; it++) {
        const int p = it & 1;                 // read buf p, write buf 1-p
        float xnext = 0.0f;
        if (tid < NCOL) xnext = x[(j0 + tid) * SEQT + it + 2];

        const uint32_t rowBt = rowBb + (uint32_t)p * 16384;

        float d32[16];
#pragma unroll
        for (int q = 0; q < 16; q++) d32[q] = bias[q];
        uint32_t dlo[4][2];
#pragma unroll
        for (int q = 0; q < 4; q++) { dlo[q][0] = 0u; dlo[q][1] = 0u; }

#pragma unroll
        for (int ks = 0; ks < 16; ks++) {
            uint32_t bh4[4], bl4[4];
            LDSM4T(bh4, rowBt + (uint32_t)ks * 512);
            LDSM4T(bl4, rowBt + 8192 + (uint32_t)ks * 512);
            uint4 a8 = *(const uint4*)(fp8b + ks * 512);
            uint32_t al[8];
            unp2(a8.x, al[0], al[1]);
            unp2(a8.y, al[2], al[3]);
            unp2(a8.z, al[4], al[5]);
            unp2(a8.w, al[6], al[7]);
            // main pass: W_hi . h_hi  (f32 accum)
            mma_f32(&d32[0],  ahi0[ks], bh4[0], bh4[1]);
            mma_f32(&d32[4],  ahi0[ks], bh4[2], bh4[3]);
            mma_f32(&d32[8],  ahi1[ks], bh4[0], bh4[1]);
            mma_f32(&d32[12], ahi1[ks], bh4[2], bh4[3]);
            // correction passes (x 2^8): f16 accum
            mma_f16(dlo[0], al,       bh4[0], bh4[1]);
            mma_f16(dlo[0], ahi0[ks], bl4[0], bl4[1]);
            mma_f16(dlo[1], al,       bh4[2], bh4[3]);
            mma_f16(dlo[1], ahi0[ks], bl4[2], bl4[3]);
            mma_f16(dlo[2], al + 4,   bh4[0], bh4[1]);
            mma_f16(dlo[2], ahi1[ks], bl4[0], bl4[1]);
            mma_f16(dlo[3], al + 4,   bh4[2], bh4[3]);
            mma_f16(dlo[3], ahi1[ks], bl4[2], bl4[3]);
        }

        // ---- epilogue: h = tanh(d32 + dlo*2^-8 + Whx*x) -> buf 1-p ----
        const uint32_t xsl = (uint32_t)(SM_XR + p * 64);
        const uint32_t bufw = (uint32_t)(SM_B + (1 - p) * 16384);
        const float2 xva = *(const float2*)(smc + xsl + lr * 4);        // n = lr, lr+1
        const float2 xvb = *(const float2*)(smc + xsl + 32 + lr * 4);   // n = 8+lr, +1
#pragma unroll
        for (int tm = 0; tm < 2; tm++)
#pragma unroll
            for (int tn = 0; tn < 2; tn++) {
                float2 lo01 = __half22float2(*(__half2*)&dlo[tm * 2 + tn][0]);
                float2 lo23 = __half22float2(*(__half2*)&dlo[tm * 2 + tn][1]);
                float lov[4] = {lo01.x, lo01.y, lo23.x, lo23.y};
                const float xve = tn ? xvb.x : xva.x;
                const float xvo = tn ? xvb.y : xva.y;
                float hv[4];
#pragma unroll
                for (int e = 0; e < 4; e++) {
                    int q = tm * 8 + tn * 4 + e;
                    float xv = (e & 1) ? xvo : xve;
                    float pre = fmaf(wx[tm][e >> 1], xv, fmaf(lov[e], INVSCALE, d32[q]));
                    hv[e] = tanh_fast(pre);
                }
#pragma unroll
                for (int d = 0; d < 2; d++) {
                    float h0 = hv[2 * d], h1 = hv[2 * d + 1];
                    __half2 hi2 = __floats2half2_rn(h0, h1);
                    __half2 lo2 = __floats2half2_rn((h0 - __low2float(hi2)) * SCALE,
                                                    (h1 - __high2float(hi2)) * SCALE);
                    uint32_t ba = (sb8[tm * 2 + d] >> (16 * tn)) & 0xFFFFu;
                    *(uint32_t*)(smc + bufw + ba) = *(uint32_t*)&hi2;
                    *(uint32_t*)(smc + bufw + 8192 + ba) = *(uint32_t*)&lo2;
                }
            }
        if (tid < NCOL) *(float*)(smc + SM_XR + (1 - p) * 64 + tid * 4) = xnext;
        __syncthreads();
    }

    // ================= projection: out = Wph @ h + bp =================
    // final h lives in buf0 (it=509 wrote buf 1-p = 0)
    if (tid < 10 * NCOL) {
        const int c = tid >> 4, j = tid & 15;
        float s = bp[c * BATCH + j0 + j];
        const float* wr = Wph + c * HDIM;
#pragma unroll 8
        for (int k = 0; k < HDIM; k++) {
            uint32_t off = haddr(k, j);
            float hv = __half2float(*(__half*)(smc + SM_B + off)) +
                       __half2float(*(__half*)(smc + SM_B + 8192 + off)) * INVSCALE;
            s = fmaf(wr[k], hv, s);
        }
        out[(j0 + j) * 10 + c] = s;
    }
}

extern "C" void kernel_launch(void* const* d_in, const int* in_sizes, int n_in,
                              void* d_out, int out_size) {
    const float* x   = (const float*)d_in[0];
    const float* Whx = (const float*)d_in[1];
    const float* Whh = (const float*)d_in[2];
    const float* Wph = (const float*)d_in[3];
    const float* bh  = (const float*)d_in[4];
    const float* bp  = (const float*)d_in[5];
    float* out = (float*)d_out;

    cudaFuncSetAttribute(VanillaRNN_54984171323420_kernel,
                         cudaFuncAttributeMaxDynamicSharedMemorySize, SM_TOTAL);
    VanillaRNN_54984171323420_kernel<<<NBLK, NTHR, SM_TOTAL>>>(
        x, Whx, Whh, Wph, bh, bp, out);
}